// round 5
// baseline (speedup 1.0000x reference)
#include <cuda_runtime.h>
#include <cuda_bf16.h>
#include <math.h>

#define B_ 4
#define T_ 1024
#define D_ 1024
#define H_ 16
#define DK_ 64
#define BTD (B_*T_*D_)

// ---------------- scratch (device globals; no allocation allowed) ----------------
__device__ float g_Q[BTD];      // [B,H,T,DK]
__device__ float g_K[BTD];      // [B,H,T,DK]
__device__ float g_V[BTD];      // [B,H,T,DK]
__device__ float g_attn[BTD];   // [B,T,D]
__device__ float g_c[B_];
__device__ float g_tau[B_];
__device__ float g_vmean[B_*H_*DK_];

// ---------------- tf32 helpers ----------------
__device__ __forceinline__ void split_tf32(float x, float& hi, float& lo) {
    unsigned h;
    asm("cvt.rna.tf32.f32 %0, %1;" : "=r"(h) : "f"(x));
    hi = __uint_as_float(h);
    float r = x - hi;
    unsigned l;
    asm("cvt.rna.tf32.f32 %0, %1;" : "=r"(l) : "f"(r));
    lo = __uint_as_float(l);
}

__device__ __forceinline__ void mma_tf32(float c[4], const unsigned a[4], const unsigned b[2]) {
    asm volatile(
        "mma.sync.aligned.m16n8k8.row.col.f32.tf32.tf32.f32 "
        "{%0,%1,%2,%3}, {%4,%5,%6,%7}, {%8,%9}, {%0,%1,%2,%3};"
        : "+f"(c[0]), "+f"(c[1]), "+f"(c[2]), "+f"(c[3])
        : "r"(a[0]), "r"(a[1]), "r"(a[2]), "r"(a[3]), "r"(b[0]), "r"(b[1]));
}

// ---------------- 3xTF32 GEMM: Y = X @ W^T + bias ----------------
// X:[M,K] row-major, W:[N,K] row-major. BM=BN=128, BK=16, 256 threads (8 warps).
// Warp tile 32x64 (warp_m = wid&3, warp_n = wid>>2).
// MODE 0: Y[m*N+n]   MODE 1: head-split  Y[((b*H+h)*T+t)*DK+dk]
#define SM_STRIDE 20   // 16 + 4 pad -> conflict-free for frag access pattern

template<int MODE>
__global__ void __launch_bounds__(256)
gemm_tf32(const float* __restrict__ X, const float* __restrict__ W,
          const float* __restrict__ bias, float* __restrict__ Y,
          int M, int N, int K)
{
    __shared__ float Xh[128][SM_STRIDE], Xl[128][SM_STRIDE];
    __shared__ float Wh[128][SM_STRIDE], Wl[128][SM_STRIDE];

    const int tid  = threadIdx.x;
    const int lane = tid & 31;
    const int wid  = tid >> 5;
    const int wm   = wid & 3;          // 0..3 -> 32-row slab
    const int wn   = wid >> 2;         // 0..1 -> 64-col slab
    const int bm   = blockIdx.y * 128;
    const int bn   = blockIdx.x * 128;

    const int lr = lane >> 2;          // 0..7
    const int lc = lane & 3;           // 0..3

    float C[2][8][4];
#pragma unroll
    for (int mt = 0; mt < 2; mt++)
#pragma unroll
        for (int nt = 0; nt < 8; nt++)
#pragma unroll
            for (int j = 0; j < 4; j++) C[mt][nt][j] = 0.f;

    // prefetch first chunk (each thread: 2 float4 from X, 2 from W)
    float4 xr[2], wr[2];
#pragma unroll
    for (int i = 0; i < 2; i++) {
        const int idx = tid + i * 256;
        const int r = idx >> 2, cg = (idx & 3) * 4;
        xr[i] = *(const float4*)&X[(size_t)(bm + r) * K + cg];
        wr[i] = *(const float4*)&W[(size_t)(bn + r) * K + cg];
    }

    for (int k0 = 0; k0 < K; k0 += 16) {
        // write current chunk to smem (split hi/lo)
#pragma unroll
        for (int i = 0; i < 2; i++) {
            const int idx = tid + i * 256;
            const int r = idx >> 2, cg = (idx & 3) * 4;
            float vx[4] = { xr[i].x, xr[i].y, xr[i].z, xr[i].w };
            float vw[4] = { wr[i].x, wr[i].y, wr[i].z, wr[i].w };
#pragma unroll
            for (int j = 0; j < 4; j++) {
                float h, l;
                split_tf32(vx[j], h, l);
                Xh[r][cg + j] = h; Xl[r][cg + j] = l;
                split_tf32(vw[j], h, l);
                Wh[r][cg + j] = h; Wl[r][cg + j] = l;
            }
        }
        __syncthreads();

        // prefetch next chunk
        if (k0 + 16 < K) {
#pragma unroll
            for (int i = 0; i < 2; i++) {
                const int idx = tid + i * 256;
                const int r = idx >> 2, cg = (idx & 3) * 4;
                xr[i] = *(const float4*)&X[(size_t)(bm + r) * K + k0 + 16 + cg];
                wr[i] = *(const float4*)&W[(size_t)(bn + r) * K + k0 + 16 + cg];
            }
        }

        // two k-steps of 8
#pragma unroll
        for (int ks = 0; ks < 2; ks++) {
            const int kb = ks * 8;
            unsigned Ah[2][4], Al[2][4];
#pragma unroll
            for (int mt = 0; mt < 2; mt++) {
                const int rb = wm * 32 + mt * 16 + lr;
                const int kc = kb + lc;
                Ah[mt][0] = __float_as_uint(Xh[rb    ][kc    ]);
                Ah[mt][1] = __float_as_uint(Xh[rb + 8][kc    ]);
                Ah[mt][2] = __float_as_uint(Xh[rb    ][kc + 4]);
                Ah[mt][3] = __float_as_uint(Xh[rb + 8][kc + 4]);
                Al[mt][0] = __float_as_uint(Xl[rb    ][kc    ]);
                Al[mt][1] = __float_as_uint(Xl[rb + 8][kc    ]);
                Al[mt][2] = __float_as_uint(Xl[rb    ][kc + 4]);
                Al[mt][3] = __float_as_uint(Xl[rb + 8][kc + 4]);
            }
            unsigned Bh[8][2], Bl[8][2];
#pragma unroll
            for (int nt = 0; nt < 8; nt++) {
                const int nb = wn * 64 + nt * 8 + lr;
                const int kc = kb + lc;
                Bh[nt][0] = __float_as_uint(Wh[nb][kc    ]);
                Bh[nt][1] = __float_as_uint(Wh[nb][kc + 4]);
                Bl[nt][0] = __float_as_uint(Wl[nb][kc    ]);
                Bl[nt][1] = __float_as_uint(Wl[nb][kc + 4]);
            }
#pragma unroll
            for (int mt = 0; mt < 2; mt++)
#pragma unroll
                for (int nt = 0; nt < 8; nt++) {
                    mma_tf32(C[mt][nt], Al[mt], Bh[nt]);   // lo*hi
                    mma_tf32(C[mt][nt], Ah[mt], Bl[nt]);   // hi*lo
                    mma_tf32(C[mt][nt], Ah[mt], Bh[nt]);   // hi*hi
                }
        }
        __syncthreads();
    }

    // epilogue: bias add + store
#pragma unroll
    for (int mt = 0; mt < 2; mt++) {
#pragma unroll
        for (int nt = 0; nt < 8; nt++) {
            const int row = bm + wm * 32 + mt * 16 + lr;
            const int col = bn + wn * 64 + nt * 8 + lc * 2;
            const float b0 = bias[col], b1 = bias[col + 1];
#pragma unroll
            for (int half = 0; half < 2; half++) {
                const int m = row + half * 8;
                const float v0 = C[mt][nt][half * 2 + 0] + b0;
                const float v1 = C[mt][nt][half * 2 + 1] + b1;
                if (MODE == 0) {
                    float2* p = (float2*)&Y[(size_t)m * N + col];
                    *p = make_float2(v0, v1);
                } else {
                    const int b  = m >> 10;
                    const int t  = m & 1023;
                    const int h  = col >> 6;
                    const int dk = col & 63;
                    float2* p = (float2*)&g_Q[0];  // placeholder type; real below
                    (void)p;
                    float2* q = (float2*)&Y[((size_t)(b * H_ + h) * T_ + t) * DK_ + dk];
                    *q = make_float2(v0, v1);
                }
            }
        }
    }
}

// ---------------- gate: c, tau, u per batch ----------------
__global__ void gate_kernel(const float* __restrict__ Wg1, const float* __restrict__ bg1,
                            const float* __restrict__ Wg2, const float* __restrict__ bg2,
                            float* __restrict__ u_out)
{
    const int b = blockIdx.x;
    const int tid = threadIdx.x;
    __shared__ float sh1[256], sh2[256];
    float s1 = 0.f, s2 = 0.f;
    for (int d = tid; d < D_; d += 256) {
        const int h  = d >> 6;
        const int dk = d & 63;
        const float ctx = g_Q[((size_t)(b*H_ + h) * T_ + 0) * DK_ + dk];
        s1 += ctx * Wg1[d];
        s2 += ctx * Wg2[d];
    }
    sh1[tid] = s1; sh2[tid] = s2;
    __syncthreads();
    for (int off = 128; off > 0; off >>= 1) {
        if (tid < off) { sh1[tid] += sh1[tid+off]; sh2[tid] += sh2[tid+off]; }
        __syncthreads();
    }
    if (tid == 0) {
        const float a1 = sh1[0] + bg1[0];
        const float a2 = sh2[0] + bg2[0];
        const float q1 = 1.f / (1.f + expf(-a1));
        const float q2 = 1.f / (1.f + expf(-a2));
        float c = q1 * q2;
        c = fminf(fmaxf(c, 1e-8f), 1.0f);
        g_c[b]   = c;
        g_tau[b] = (c < 0.3f) ? (1.0f / c) : 1.0f;
        if (u_out) u_out[b] = 1.0f - c;
    }
}

// ---------------- V mean over time ----------------
__global__ void vmean_kernel()
{
    const int bh = blockIdx.x;       // 0..63
    const int d  = threadIdx.x;      // 0..63
    const float* Vp = g_V + (size_t)bh * T_ * DK_;
    float s = 0.f;
    for (int t = 0; t < T_; t++) s += Vp[t * DK_ + d];
    g_vmean[bh * DK_ + d] = s * (1.0f / (float)T_);
}

// ---------------- flash attention + epistemic gating ----------------
__global__ void __launch_bounds__(128)
flash_attn_kernel()
{
    const int bh = blockIdx.x;
    const int b  = bh >> 4;
    const int h  = bh & 15;
    const int q0 = blockIdx.y * 128;
    const int tid = threadIdx.x;

    __shared__ float Ks[64 * 64];
    __shared__ float Vs[64 * 64];

    const float* Qp = g_Q + ((size_t)bh * T_ + q0) * DK_;
    const float* Kp = g_K + (size_t)bh * T_ * DK_;
    const float* Vp = g_V + (size_t)bh * T_ * DK_;

    const float tau   = g_tau[b];
    const float scale = 0.125f / tau;

    float q[64];
    {
        const float4* q4 = (const float4*)(Qp + (size_t)tid * DK_);
#pragma unroll
        for (int i = 0; i < 16; i++) {
            float4 v = q4[i];
            q[4*i+0] = v.x; q[4*i+1] = v.y; q[4*i+2] = v.z; q[4*i+3] = v.w;
        }
    }

    float o[64];
#pragma unroll
    for (int d = 0; d < 64; d++) o[d] = 0.f;
    float m = -1e30f, l = 0.f;

    for (int kt = 0; kt < T_ / 64; kt++) {
        {
            const float4* kg = (const float4*)(Kp + (size_t)kt * 64 * DK_);
            const float4* vg = (const float4*)(Vp + (size_t)kt * 64 * DK_);
            float4* ks4 = (float4*)Ks;
            float4* vs4 = (float4*)Vs;
#pragma unroll
            for (int i = 0; i < 8; i++) {
                ks4[tid + i*128] = kg[tid + i*128];
                vs4[tid + i*128] = vg[tid + i*128];
            }
        }
        __syncthreads();

#pragma unroll 2
        for (int kk = 0; kk < 64; kk++) {
            const float4* k4 = (const float4*)(Ks + kk * 64);
            float s = 0.f;
#pragma unroll
            for (int i = 0; i < 16; i++) {
                float4 kv = k4[i];
                s += q[4*i+0]*kv.x + q[4*i+1]*kv.y + q[4*i+2]*kv.z + q[4*i+3]*kv.w;
            }
            s *= scale;
            if (s > m) {
                const float corr = __expf(m - s);
                m = s;
                l *= corr;
#pragma unroll
                for (int d = 0; d < 64; d++) o[d] *= corr;
            }
            const float p = __expf(s - m);
            l += p;
            const float4* v4 = (const float4*)(Vs + kk * 64);
#pragma unroll
            for (int i = 0; i < 16; i++) {
                float4 vv = v4[i];
                o[4*i+0] += p * vv.x;
                o[4*i+1] += p * vv.y;
                o[4*i+2] += p * vv.z;
                o[4*i+3] += p * vv.w;
            }
        }
        __syncthreads();
    }

    const float c    = g_c[b];
    const float cl   = c / l;
    const float omc  = 1.0f - c;
    const float* vm  = g_vmean + bh * DK_;
    float* outp = g_attn + ((size_t)(b * T_) + q0 + tid) * D_ + h * DK_;
    float4* out4 = (float4*)outp;
#pragma unroll
    for (int i = 0; i < 16; i++) {
        float4 r;
        r.x = o[4*i+0]*cl + omc*vm[4*i+0];
        r.y = o[4*i+1]*cl + omc*vm[4*i+1];
        r.z = o[4*i+2]*cl + omc*vm[4*i+2];
        r.w = o[4*i+3]*cl + omc*vm[4*i+3];
        out4[i] = r;
    }
}

// ---------------- launch ----------------
extern "C" void kernel_launch(void* const* d_in, const int* in_sizes, int n_in,
                              void* d_out, int out_size)
{
    const float* x   = (const float*)d_in[0];
    const float* Wq  = (const float*)d_in[1];
    const float* bq  = (const float*)d_in[2];
    const float* Wk  = (const float*)d_in[3];
    const float* bk  = (const float*)d_in[4];
    const float* Wv  = (const float*)d_in[5];
    const float* bv  = (const float*)d_in[6];
    const float* Wo  = (const float*)d_in[7];
    const float* bo  = (const float*)d_in[8];
    const float* Wg1 = (const float*)d_in[9];
    const float* bg1 = (const float*)d_in[10];
    const float* Wg2 = (const float*)d_in[11];
    const float* bg2 = (const float*)d_in[12];
    float* out = (float*)d_out;

    float *pQ, *pK, *pV, *pAttn;
    cudaGetSymbolAddress((void**)&pQ,    g_Q);
    cudaGetSymbolAddress((void**)&pK,    g_K);
    cudaGetSymbolAddress((void**)&pV,    g_V);
    cudaGetSymbolAddress((void**)&pAttn, g_attn);

    const int M = B_ * T_, N = D_, K = D_;
    dim3 gemm_grid(N / 128, M / 128);   // (8, 32)

    gemm_tf32<1><<<gemm_grid, 256>>>(x, Wq, bq, pQ, M, N, K);
    gemm_tf32<1><<<gemm_grid, 256>>>(x, Wk, bk, pK, M, N, K);
    gemm_tf32<1><<<gemm_grid, 256>>>(x, Wv, bv, pV, M, N, K);

    float* u_out = (out_size >= BTD + B_) ? (out + (out_size - B_)) : nullptr;
    gate_kernel<<<B_, 256>>>(Wg1, bg1, Wg2, bg2, u_out);

    vmean_kernel<<<B_ * H_, DK_>>>();

    dim3 attn_grid(B_ * H_, T_ / 128);
    flash_attn_kernel<<<attn_grid, 128>>>(); 

    gemm_tf32<0><<<gemm_grid, 256>>>(pAttn, Wo, bo, out, M, N, K);
}

// round 6
// speedup vs baseline: 2.4581x; 2.4581x over previous
#include <cuda_runtime.h>
#include <cuda_bf16.h>
#include <math.h>

#define B_ 4
#define T_ 1024
#define D_ 1024
#define H_ 16
#define DK_ 64
#define BTD (B_*T_*D_)
typedef __nv_bfloat16 bf16;

// ---------------- scratch ----------------
__device__ bf16 g_Xh[BTD], g_Xl[BTD];
__device__ bf16 g_Wh[4*D_*D_], g_Wl[4*D_*D_];
__device__ bf16 g_Qh[BTD], g_Ql[BTD];
__device__ bf16 g_Kh[BTD], g_Kl[BTD];
__device__ bf16 g_Vh[BTD], g_Vl[BTD];
__device__ bf16 g_Ah[BTD], g_Al[BTD];
__device__ float g_Qf[B_*D_];          // first-token Q rows (for gate)
__device__ float g_c[B_], g_tau[B_];
__device__ float g_vmean[B_*H_*DK_];

// ---------------- helpers ----------------
__device__ __forceinline__ unsigned smem_u32(const void* p) {
    return (unsigned)__cvta_generic_to_shared(p);
}
__device__ __forceinline__ void ldsm4(unsigned& r0, unsigned& r1, unsigned& r2, unsigned& r3, unsigned a) {
    asm volatile("ldmatrix.sync.aligned.m8n8.x4.shared.b16 {%0,%1,%2,%3},[%4];"
        : "=r"(r0), "=r"(r1), "=r"(r2), "=r"(r3) : "r"(a));
}
__device__ __forceinline__ void ldsm4t(unsigned& r0, unsigned& r1, unsigned& r2, unsigned& r3, unsigned a) {
    asm volatile("ldmatrix.sync.aligned.m8n8.x4.trans.shared.b16 {%0,%1,%2,%3},[%4];"
        : "=r"(r0), "=r"(r1), "=r"(r2), "=r"(r3) : "r"(a));
}
__device__ __forceinline__ void mma_bf16(float c[4], const unsigned a[4], const unsigned b[2]) {
    asm volatile("mma.sync.aligned.m16n8k16.row.col.f32.bf16.bf16.f32 "
        "{%0,%1,%2,%3},{%4,%5,%6,%7},{%8,%9},{%0,%1,%2,%3};"
        : "+f"(c[0]), "+f"(c[1]), "+f"(c[2]), "+f"(c[3])
        : "r"(a[0]), "r"(a[1]), "r"(a[2]), "r"(a[3]), "r"(b[0]), "r"(b[1]));
}
__device__ __forceinline__ float ex2f(float x) {
    float y; asm("ex2.approx.f32 %0,%1;" : "=f"(y) : "f"(x)); return y;
}
__device__ __forceinline__ unsigned pkbf2(float a, float b) {  // a->low, b->high
    unsigned r; asm("cvt.rn.bf16x2.f32 %0,%1,%2;" : "=r"(r) : "f"(b), "f"(a)); return r;
}
__device__ __forceinline__ void pksplit(float x, float y, unsigned& hi, unsigned& lo) {
    bf16 hx = __float2bfloat16(x), hy = __float2bfloat16(y);
    hi = ((unsigned)__bfloat16_as_ushort(hy) << 16) | (unsigned)__bfloat16_as_ushort(hx);
    lo = pkbf2(x - __bfloat162float(hx), y - __bfloat162float(hy));
}
__device__ __forceinline__ void split4(float4 v, uint2& hi, uint2& lo) {
    unsigned h0, l0_, h1, l1_;
    pksplit(v.x, v.y, h0, l0_);
    pksplit(v.z, v.w, h1, l1_);
    hi.x = h0; hi.y = h1; lo.x = l0_; lo.y = l1_;
}
// fast exp2: deg-5 poly + magic rounding; rel err ~2.4e-6; FFMA pipe only
__device__ __forceinline__ float exp2p(float y) {
    y = fmaxf(y, -100.f);
    float t = y + 12582912.f;
    int   i = __float_as_int(t);
    float n = t - 12582912.f;
    float f = y - n;
    float p = 0.0013333558f;
    p = fmaf(p, f, 0.0096181291f);
    p = fmaf(p, f, 0.0555041087f);
    p = fmaf(p, f, 0.2402264476f);
    p = fmaf(p, f, 0.6931471806f);
    p = fmaf(p, f, 1.0f);
    return __int_as_float(__float_as_int(p) + (i << 23));
}

// ---------------- preprocessing: split x and all W into bf16 hi/lo ----------------
__global__ void __launch_bounds__(256) split_all(
    const float* __restrict__ x, const float* __restrict__ wq,
    const float* __restrict__ wk, const float* __restrict__ wv,
    const float* __restrict__ wo)
{
    const unsigned NX = BTD/4, NW = D_*D_/4;
    unsigned i = blockIdx.x*256u + threadIdx.x;
    const float* src; bf16 *dh, *dl; unsigned off;
    if (i < NX) { src = x; dh = g_Xh; dl = g_Xl; off = i; }
    else {
        unsigned j = i - NX; unsigned w = j / NW; off = j % NW;
        src = (w==0) ? wq : (w==1) ? wk : (w==2) ? wv : wo;
        dh = g_Wh + (size_t)w*D_*D_; dl = g_Wl + (size_t)w*D_*D_;
    }
    float4 v = ((const float4*)src)[off];
    uint2 hi, lo; split4(v, hi, lo);
    ((uint2*)dh)[off] = hi; ((uint2*)dl)[off] = lo;
}

// ---------------- bf16x3 GEMM: Y = A @ B^T + bias ----------------
// A:[M,K]=(Ah+Al), B:[N,K]=(Bh+Bl) bf16. BM=BN=128, BK=32, 256 thr, 8 warps (32x64 warp tile).
// MODE 0: fp32 Y[m*N+n].  MODE 1: bf16 hi/lo head-split + optional fp32 first-token rows.
#define GP 40   // smem pitch (bf16); 80B rows -> ldsm conflict-free
template<int MODE>
__global__ void __launch_bounds__(256)
gemm_bf16(const bf16* __restrict__ Agh, const bf16* __restrict__ Agl,
          const bf16* __restrict__ Bgh, const bf16* __restrict__ Bgl,
          const float* __restrict__ bias,
          float* __restrict__ Yf, bf16* __restrict__ Yh, bf16* __restrict__ Yl,
          float* __restrict__ Qf)
{
    __shared__ bf16 sAh[128*GP], sAl[128*GP], sBh[128*GP], sBl[128*GP];
    const int tid = threadIdx.x, lane = tid & 31, wid = tid >> 5;
    const int wm = wid & 3, wn = wid >> 2;
    const int bm = blockIdx.y*128, bn = blockIdx.x*128;
    const int K = D_;

    float C[2][8][4] = {};

    const int r0 = tid >> 2, cc0 = (tid & 3)*8;   // rows r0, r0+64; 16B chunk cc0
    const size_t ga0 = (size_t)(bm + r0)*K + cc0;
    const size_t ga1 = (size_t)(bm + r0 + 64)*K + cc0;
    const size_t gb0 = (size_t)(bn + r0)*K + cc0;
    const size_t gb1 = gb0 + (size_t)64*K;
    uint4 pah[2], pal[2], pbh[2], pbl[2];
    pah[0] = *(const uint4*)&Agh[ga0]; pah[1] = *(const uint4*)&Agh[ga1];
    pal[0] = *(const uint4*)&Agl[ga0]; pal[1] = *(const uint4*)&Agl[ga1];
    pbh[0] = *(const uint4*)&Bgh[gb0]; pbh[1] = *(const uint4*)&Bgh[gb1];
    pbl[0] = *(const uint4*)&Bgl[gb0]; pbl[1] = *(const uint4*)&Bgl[gb1];

    const int s0 = r0*GP + cc0, s1 = (r0+64)*GP + cc0;
    const unsigned uAh = smem_u32(sAh), uAl = smem_u32(sAl);
    const unsigned uBh = smem_u32(sBh), uBl = smem_u32(sBl);
    const int arow = wm*32 + (lane & 15), acol = (lane >> 4)*8;
    const int brow = wn*64 + (lane & 7) + (lane >> 4)*8, bcol = ((lane >> 3) & 1)*8;

    for (int k0 = 0; k0 < 1024; k0 += 32) {
        *(uint4*)&sAh[s0] = pah[0]; *(uint4*)&sAh[s1] = pah[1];
        *(uint4*)&sAl[s0] = pal[0]; *(uint4*)&sAl[s1] = pal[1];
        *(uint4*)&sBh[s0] = pbh[0]; *(uint4*)&sBh[s1] = pbh[1];
        *(uint4*)&sBl[s0] = pbl[0]; *(uint4*)&sBl[s1] = pbl[1];
        __syncthreads();
        if (k0 < 1024 - 32) {
            const int kn = k0 + 32;
            pah[0] = *(const uint4*)&Agh[ga0+kn]; pah[1] = *(const uint4*)&Agh[ga1+kn];
            pal[0] = *(const uint4*)&Agl[ga0+kn]; pal[1] = *(const uint4*)&Agl[ga1+kn];
            pbh[0] = *(const uint4*)&Bgh[gb0+kn]; pbh[1] = *(const uint4*)&Bgh[gb1+kn];
            pbl[0] = *(const uint4*)&Bgl[gb0+kn]; pbl[1] = *(const uint4*)&Bgl[gb1+kn];
        }
#pragma unroll
        for (int ks = 0; ks < 2; ks++) {
            unsigned Af[2][4], Al_[2][4];
#pragma unroll
            for (int mt = 0; mt < 2; mt++) {
                const unsigned off = (unsigned)(((arow + mt*16)*GP + ks*16 + acol)*2);
                ldsm4(Af[mt][0], Af[mt][1], Af[mt][2], Af[mt][3], uAh + off);
                ldsm4(Al_[mt][0], Al_[mt][1], Al_[mt][2], Al_[mt][3], uAl + off);
            }
#pragma unroll
            for (int pp = 0; pp < 4; pp++) {
                const unsigned off = (unsigned)(((brow + pp*16)*GP + ks*16 + bcol)*2);
                unsigned bh4[4], bl4[4];
                ldsm4(bh4[0], bh4[1], bh4[2], bh4[3], uBh + off);
                ldsm4(bl4[0], bl4[1], bl4[2], bl4[3], uBl + off);
#pragma unroll
                for (int mt = 0; mt < 2; mt++) {
                    mma_bf16(C[mt][2*pp],   Af[mt],  bh4+0);
                    mma_bf16(C[mt][2*pp],   Al_[mt], bh4+0);
                    mma_bf16(C[mt][2*pp],   Af[mt],  bl4+0);
                    mma_bf16(C[mt][2*pp+1], Af[mt],  bh4+2);
                    mma_bf16(C[mt][2*pp+1], Al_[mt], bh4+2);
                    mma_bf16(C[mt][2*pp+1], Af[mt],  bl4+2);
                }
            }
        }
        __syncthreads();
    }

    const int lr = lane >> 2, lc = lane & 3;
#pragma unroll
    for (int mt = 0; mt < 2; mt++)
#pragma unroll
    for (int nt = 0; nt < 8; nt++) {
        const int row = bm + wm*32 + mt*16 + lr;
        const int col = bn + wn*64 + nt*8 + lc*2;
        const float b0 = bias[col], b1 = bias[col+1];
#pragma unroll
        for (int hh = 0; hh < 2; hh++) {
            const int m = row + hh*8;
            const float v0 = C[mt][nt][hh*2+0] + b0;
            const float v1 = C[mt][nt][hh*2+1] + b1;
            if (MODE == 0) {
                *(float2*)&Yf[(size_t)m*D_ + col] = make_float2(v0, v1);
            } else {
                const int b = m >> 10, t = m & 1023, h = col >> 6, dk = col & 63;
                const size_t idx = ((size_t)(b*H_ + h)*T_ + t)*DK_ + dk;
                unsigned hi, lo; pksplit(v0, v1, hi, lo);
                *(unsigned*)&Yh[idx] = hi; *(unsigned*)&Yl[idx] = lo;
                if (Qf && t == 0) *(float2*)&Qf[b*D_ + col] = make_float2(v0, v1);
            }
        }
    }
}

// ---------------- gate ----------------
__global__ void gate_kernel(const float* __restrict__ Wg1, const float* __restrict__ bg1,
                            const float* __restrict__ Wg2, const float* __restrict__ bg2,
                            float* __restrict__ u_out)
{
    const int b = blockIdx.x, tid = threadIdx.x;
    __shared__ float sh1[256], sh2[256];
    float s1 = 0.f, s2 = 0.f;
    for (int d = tid; d < D_; d += 256) {
        const float ctx = g_Qf[b*D_ + d];
        s1 += ctx * Wg1[d]; s2 += ctx * Wg2[d];
    }
    sh1[tid] = s1; sh2[tid] = s2;
    __syncthreads();
    for (int off = 128; off > 0; off >>= 1) {
        if (tid < off) { sh1[tid] += sh1[tid+off]; sh2[tid] += sh2[tid+off]; }
        __syncthreads();
    }
    if (tid == 0) {
        const float q1 = 1.f / (1.f + expf(-(sh1[0] + bg1[0])));
        const float q2 = 1.f / (1.f + expf(-(sh2[0] + bg2[0])));
        float c = fminf(fmaxf(q1*q2, 1e-8f), 1.0f);
        g_c[b] = c;
        g_tau[b] = (c < 0.3f) ? (1.0f/c) : 1.0f;
        if (u_out) u_out[b] = 1.0f - c;
    }
}

// ---------------- V mean ----------------
__global__ void vmean_kernel()
{
    const int bh = blockIdx.x, d = threadIdx.x;
    const bf16* vh = g_Vh + (size_t)bh*T_*DK_;
    const bf16* vl = g_Vl + (size_t)bh*T_*DK_;
    float s = 0.f;
    for (int t = 0; t < T_; t++)
        s += __bfloat162float(vh[t*DK_ + d]) + __bfloat162float(vl[t*DK_ + d]);
    g_vmean[bh*DK_ + d] = s * (1.0f/(float)T_);
}

// ---------------- tensor-core flash attention + gating ----------------
// grid (B*H, T/64), 128 threads (4 warps), warp = 16 q-rows.
#define AP 72
__global__ void __launch_bounds__(128)
attn_kernel()
{
    __shared__ bf16 sKh[64*AP], sKl[64*AP], sVh[64*AP], sVl[64*AP];
    const int bh = blockIdx.x, b = bh >> 4, h = bh & 15;
    const int q0 = blockIdx.y*64;
    const int tid = threadIdx.x, lane = tid & 31, warp = tid >> 5;
    const unsigned uKh = smem_u32(sKh), uKl = smem_u32(sKl);
    const unsigned uVh = smem_u32(sVh), uVl = smem_u32(sVl);

    // stage Q tile through sK, extract A-fragments once
#pragma unroll
    for (int j = 0; j < 4; j++) {
        const int i = tid + j*128, r = i >> 3, c = (i & 7)*8;
        const size_t g = ((size_t)bh*T_ + q0 + r)*DK_ + c;
        *(uint4*)&sKh[r*AP + c] = *(const uint4*)&g_Qh[g];
        *(uint4*)&sKl[r*AP + c] = *(const uint4*)&g_Ql[g];
    }
    __syncthreads();
    unsigned qh[4][4], ql[4][4];
    {
        const int arow = warp*16 + (lane & 15), acol = (lane >> 4)*8;
#pragma unroll
        for (int kk = 0; kk < 4; kk++) {
            const unsigned off = (unsigned)((arow*AP + kk*16 + acol)*2);
            ldsm4(qh[kk][0], qh[kk][1], qh[kk][2], qh[kk][3], uKh + off);
            ldsm4(ql[kk][0], ql[kk][1], ql[kk][2], ql[kk][3], uKl + off);
        }
    }
    __syncthreads();

    const float cc  = g_c[b];
    const float sc  = (0.125f / g_tau[b]) * 1.4426950408889634f;  // scale*log2e
    float O[8][4] = {};
    float m0 = -1e30f, m1 = -1e30f, l0 = 0.f, l1 = 0.f;

    const size_t kvbase = (size_t)bh*T_*DK_;
    const int brow = (lane & 7) + (lane >> 4)*8, bcol = ((lane >> 3) & 1)*8;   // K (non-trans)
    const int vrow = (lane & 7) + ((lane >> 3) & 1)*8, vcol = (lane >> 4)*8;   // V (trans)

    for (int kt = 0; kt < 16; kt++) {
#pragma unroll
        for (int j = 0; j < 4; j++) {
            const int i = tid + j*128, r = i >> 3, c = (i & 7)*8;
            const size_t g = kvbase + (size_t)(kt*64 + r)*DK_ + c;
            const int s = r*AP + c;
            *(uint4*)&sKh[s] = *(const uint4*)&g_Kh[g];
            *(uint4*)&sKl[s] = *(const uint4*)&g_Kl[g];
            *(uint4*)&sVh[s] = *(const uint4*)&g_Vh[g];
            *(uint4*)&sVl[s] = *(const uint4*)&g_Vl[g];
        }
        __syncthreads();

        // S = Q K^T (3-term split)
        float S[8][4] = {};
#pragma unroll
        for (int kk = 0; kk < 4; kk++) {
#pragma unroll
            for (int pp = 0; pp < 4; pp++) {
                const unsigned off = (unsigned)(((brow + pp*16)*AP + kk*16 + bcol)*2);
                unsigned kh4[4], kl4[4];
                ldsm4(kh4[0], kh4[1], kh4[2], kh4[3], uKh + off);
                ldsm4(kl4[0], kl4[1], kl4[2], kl4[3], uKl + off);
                mma_bf16(S[2*pp],   qh[kk], kh4+0);
                mma_bf16(S[2*pp],   ql[kk], kh4+0);
                mma_bf16(S[2*pp],   qh[kk], kl4+0);
                mma_bf16(S[2*pp+1], qh[kk], kh4+2);
                mma_bf16(S[2*pp+1], ql[kk], kh4+2);
                mma_bf16(S[2*pp+1], qh[kk], kl4+2);
            }
        }
        // online softmax (base 2)
        float mx0 = -1e30f, mx1 = -1e30f;
#pragma unroll
        for (int nt = 0; nt < 8; nt++) {
            S[nt][0] *= sc; S[nt][1] *= sc; S[nt][2] *= sc; S[nt][3] *= sc;
            mx0 = fmaxf(mx0, fmaxf(S[nt][0], S[nt][1]));
            mx1 = fmaxf(mx1, fmaxf(S[nt][2], S[nt][3]));
        }
        mx0 = fmaxf(mx0, __shfl_xor_sync(0xffffffffu, mx0, 1));
        mx0 = fmaxf(mx0, __shfl_xor_sync(0xffffffffu, mx0, 2));
        mx1 = fmaxf(mx1, __shfl_xor_sync(0xffffffffu, mx1, 1));
        mx1 = fmaxf(mx1, __shfl_xor_sync(0xffffffffu, mx1, 2));
        const float nm0 = fmaxf(m0, mx0), nm1 = fmaxf(m1, mx1);
        const float cr0 = ex2f(m0 - nm0), cr1 = ex2f(m1 - nm1);
        m0 = nm0; m1 = nm1;
        float s0 = 0.f, s1 = 0.f;
#pragma unroll
        for (int nt = 0; nt < 8; nt++) {
            const float p0 = exp2p(S[nt][0] - m0), p1 = exp2p(S[nt][1] - m0);
            const float p2 = exp2p(S[nt][2] - m1), p3 = exp2p(S[nt][3] - m1);
            S[nt][0] = p0; S[nt][1] = p1; S[nt][2] = p2; S[nt][3] = p3;
            s0 += p0 + p1; s1 += p2 + p3;
            O[nt][0] *= cr0; O[nt][1] *= cr0; O[nt][2] *= cr1; O[nt][3] *= cr1;
        }
        s0 += __shfl_xor_sync(0xffffffffu, s0, 1);
        s0 += __shfl_xor_sync(0xffffffffu, s0, 2);
        s1 += __shfl_xor_sync(0xffffffffu, s1, 1);
        s1 += __shfl_xor_sync(0xffffffffu, s1, 2);
        l0 = l0*cr0 + s0; l1 = l1*cr1 + s1;

        // O += P V (3-term split), P converted in registers
#pragma unroll
        for (int kq = 0; kq < 4; kq++) {
            unsigned ah[4], al[4];
            pksplit(S[2*kq][0],   S[2*kq][1],   ah[0], al[0]);
            pksplit(S[2*kq][2],   S[2*kq][3],   ah[1], al[1]);
            pksplit(S[2*kq+1][0], S[2*kq+1][1], ah[2], al[2]);
            pksplit(S[2*kq+1][2], S[2*kq+1][3], ah[3], al[3]);
#pragma unroll
            for (int pp = 0; pp < 4; pp++) {
                const unsigned off = (unsigned)(((kq*16 + vrow)*AP + pp*16 + vcol)*2);
                unsigned vh4[4], vl4[4];
                ldsm4t(vh4[0], vh4[1], vh4[2], vh4[3], uVh + off);
                ldsm4t(vl4[0], vl4[1], vl4[2], vl4[3], uVl + off);
                mma_bf16(O[2*pp],   ah, vh4+0);
                mma_bf16(O[2*pp],   al, vh4+0);
                mma_bf16(O[2*pp],   ah, vl4+0);
                mma_bf16(O[2*pp+1], ah, vh4+2);
                mma_bf16(O[2*pp+1], al, vh4+2);
                mma_bf16(O[2*pp+1], ah, vl4+2);
            }
        }
        __syncthreads();
    }

    // epilogue: out = c*O/l + (1-c)*vmean, write bf16 hi/lo [B,T,D]
    const int lr = lane >> 2, lc = lane & 3;
    const float inv0 = cc / l0, inv1 = cc / l1, omc = 1.f - cc;
    const int t0r = q0 + warp*16 + lr;
#pragma unroll
    for (int nt = 0; nt < 8; nt++) {
        const int dloc = nt*8 + lc*2;
        const float vm0 = g_vmean[bh*DK_ + dloc], vm1 = g_vmean[bh*DK_ + dloc + 1];
        const float a0 = O[nt][0]*inv0 + omc*vm0, a1 = O[nt][1]*inv0 + omc*vm1;
        const float a2 = O[nt][2]*inv1 + omc*vm0, a3 = O[nt][3]*inv1 + omc*vm1;
        const size_t i0 = ((size_t)(b*T_) + t0r)*D_ + h*DK_ + dloc;
        const size_t i1 = i0 + (size_t)8*D_;
        unsigned hi, lo;
        pksplit(a0, a1, hi, lo); *(unsigned*)&g_Ah[i0] = hi; *(unsigned*)&g_Al[i0] = lo;
        pksplit(a2, a3, hi, lo); *(unsigned*)&g_Ah[i1] = hi; *(unsigned*)&g_Al[i1] = lo;
    }
}

// ---------------- launch ----------------
extern "C" void kernel_launch(void* const* d_in, const int* in_sizes, int n_in,
                              void* d_out, int out_size)
{
    const float* x   = (const float*)d_in[0];
    const float* Wq  = (const float*)d_in[1];
    const float* bq  = (const float*)d_in[2];
    const float* Wk  = (const float*)d_in[3];
    const float* bk  = (const float*)d_in[4];
    const float* Wv  = (const float*)d_in[5];
    const float* bv  = (const float*)d_in[6];
    const float* Wo  = (const float*)d_in[7];
    const float* bo  = (const float*)d_in[8];
    const float* Wg1 = (const float*)d_in[9];
    const float* bg1 = (const float*)d_in[10];
    const float* Wg2 = (const float*)d_in[11];
    const float* bg2 = (const float*)d_in[12];
    float* out = (float*)d_out;

    bf16 *pXh, *pXl, *pWh, *pWl, *pQh, *pQl, *pKh, *pKl, *pVh, *pVl, *pAh, *pAl;
    float *pQf;
    cudaGetSymbolAddress((void**)&pXh, g_Xh); cudaGetSymbolAddress((void**)&pXl, g_Xl);
    cudaGetSymbolAddress((void**)&pWh, g_Wh); cudaGetSymbolAddress((void**)&pWl, g_Wl);
    cudaGetSymbolAddress((void**)&pQh, g_Qh); cudaGetSymbolAddress((void**)&pQl, g_Ql);
    cudaGetSymbolAddress((void**)&pKh, g_Kh); cudaGetSymbolAddress((void**)&pKl, g_Kl);
    cudaGetSymbolAddress((void**)&pVh, g_Vh); cudaGetSymbolAddress((void**)&pVl, g_Vl);
    cudaGetSymbolAddress((void**)&pAh, g_Ah); cudaGetSymbolAddress((void**)&pAl, g_Al);
    cudaGetSymbolAddress((void**)&pQf, g_Qf);

    const size_t DD = (size_t)D_*D_;

    // 1. split x + all W into bf16 hi/lo
    split_all<<<(BTD/4 + 4*D_*D_/4)/256, 256>>>(x, Wq, Wk, Wv, Wo);

    // 2. projections (bf16x3, head-split bf16 out; Q also writes fp32 t=0 rows)
    dim3 gg(8, 32);
    gemm_bf16<1><<<gg, 256>>>(pXh, pXl, pWh,        pWl,        bq, nullptr, pQh, pQl, pQf);
    gemm_bf16<1><<<gg, 256>>>(pXh, pXl, pWh + DD,   pWl + DD,   bk, nullptr, pKh, pKl, nullptr);
    gemm_bf16<1><<<gg, 256>>>(pXh, pXl, pWh + 2*DD, pWl + 2*DD, bv, nullptr, pVh, pVl, nullptr);

    // 3. gate + vmean
    float* u_out = (out_size >= BTD + B_) ? (out + (out_size - B_)) : nullptr;
    gate_kernel<<<B_, 256>>>(Wg1, bg1, Wg2, bg2, u_out);
    vmean_kernel<<<B_*H_, DK_>>>();

    // 4. flash attention (tensor cores)
    attn_kernel<<<dim3(B_*H_, T_/64), 128>>>();

    // 5. output projection
    gemm_bf16<0><<<gg, 256>>>(pAh, pAl, pWh + 3*DD, pWl + 3*DD, bo, out, nullptr, nullptr, nullptr);
}